// round 6
// baseline (speedup 1.0000x reference)
#include <cuda_runtime.h>
#include <cuda_bf16.h>
#include <mma.h>

using namespace nvcuda;
typedef __nv_bfloat16 bh;

// Problem constants
#define BB 8
#define NN 512
#define SS 96
#define HH 256
#define NHH 8
#define HDD 32
#define OUTD 4
#define MQ (BB*NN)   // 4096
#define MK (BB*SS)   // 768

// Scratch (device globals — no allocation allowed)
__device__ float g_Wqp[HH*HH];       // Wq @ Ws
__device__ float g_bqp[HH];
__device__ float g_W1p[HH*HH];       // W1 @ Wao
__device__ float g_b1p[HH];
__device__ float g_Wkvp[2*HH*HH];    // [Wk@Wt ; Wv@Wt]
__device__ float g_bkvp[2*HH];
__device__ float g_q [MQ*HH];
__device__ float g_k [MK*HH];
__device__ float g_v [MK*HH];
__device__ float g_ctx[MQ*HH];
__device__ float g_fu [MQ*HH];
__device__ float g_h2 [MQ*(HH/2)];

// ---------------------------------------------------------------------------
// fp32 -> (hi, lo) bf16 split, packed 4-wide into two 8B smem stores.
// ---------------------------------------------------------------------------
__device__ __forceinline__ void cvt8(bh* ph, bh* pl, float4 v) {
    float x[4] = {v.x, v.y, v.z, v.w};
    unsigned h[4], l[4];
    #pragma unroll
    for (int i = 0; i < 4; i++) {
        __nv_bfloat16 hb = __float2bfloat16(x[i]);
        float r = x[i] - __bfloat162float(hb);
        __nv_bfloat16 lb = __float2bfloat16(r);
        h[i] = __bfloat16_as_ushort(hb);
        l[i] = __bfloat16_as_ushort(lb);
    }
    uint2 hv = make_uint2(h[0] | (h[1] << 16), h[2] | (h[3] << 16));
    uint2 lv = make_uint2(l[0] | (l[1] << 16), l[2] | (l[3] << 16));
    *(uint2*)ph = hv;
    *(uint2*)pl = lv;
}

// ---------------------------------------------------------------------------
// Tensor-core NT GEMM with fp32->bf16 hi/lo split (3-product compensation).
// C[m,n] = sum_k A[m,k]*W[n,k] + bias[n]  (optional ReLU; optional col split)
// A:(M,K) rm fp32, W:(N,K) rm fp32. M%64==0, N%64==0, K%32==0.
// 256 thr = 8 warps; 64x64 tile; warp = 16x32 via 2 wmma 16x16x16 frags.
// Per 32-wide fp32 k-chunk: products hi*hi + lo*hi + hi*lo on HMMA.
// Double-buffered smem; staging epilogue aliased over tile smem.
// ---------------------------------------------------------------------------
template<int RELU, int SPLIT>
__global__ void __launch_bounds__(256) gemm_bf16(
    const float* __restrict__ A, const float* __restrict__ Wg,
    const float* __restrict__ bias, float* __restrict__ C0,
    float* __restrict__ C1, int M, int N, int K)
{
    __shared__ __align__(16) char smem_raw[40960];  // 2 bufs x 4 mats x 64x40 bf16
    bh* sb = (bh*)smem_raw;
    float (*Cs)[68] = (float(*)[68])smem_raw;       // 64x68 fp32 staging (alias)

    const int n0 = blockIdx.x * 64;
    const int m0 = blockIdx.y * 64;
    const int tid = threadIdx.x;
    const int wid = tid >> 5;
    const int wm = wid >> 1;          // 0..3 : warp m-tile (16 rows)
    const int wn = wid & 1;           // 0..1 : warp n-tile (32 cols)
    const int r0 = tid >> 3;          // 0..31 : load row
    const int c  = (tid & 7) * 4;     // 0..28 : load k offset

    const float* Ap0 = A  + (m0 + r0) * K + c;
    const float* Ap1 = A  + (m0 + r0 + 32) * K + c;
    const float* Wp0 = Wg + (n0 + r0) * K + c;
    const float* Wp1 = Wg + (n0 + r0 + 32) * K + c;

    wmma::fragment<wmma::accumulator, 16, 16, 16, float> cf[2];
    wmma::fill_fragment(cf[0], 0.0f);
    wmma::fill_fragment(cf[1], 0.0f);

    float4 ra0 = *(const float4*)Ap0;
    float4 ra1 = *(const float4*)Ap1;
    float4 rw0 = *(const float4*)Wp0;
    float4 rw1 = *(const float4*)Wp1;

    // tile(buf, mat): mat 0=Ah 1=Al 2=Wh 3=Wl ; each 64 rows x 40 bf16
    #define TILE(buf, mat) (sb + (((buf)*4 + (mat)) * 64 * 40))

    // stash chunk 0
    {
        bh *Ah = TILE(0,0), *Al = TILE(0,1), *Wh = TILE(0,2), *Wl = TILE(0,3);
        cvt8(Ah + r0*40 + c,      Al + r0*40 + c,      ra0);
        cvt8(Ah + (r0+32)*40 + c, Al + (r0+32)*40 + c, ra1);
        cvt8(Wh + r0*40 + c,      Wl + r0*40 + c,      rw0);
        cvt8(Wh + (r0+32)*40 + c, Wl + (r0+32)*40 + c, rw1);
    }
    __syncthreads();

    const int T = K >> 5;
    int buf = 0;
    for (int t = 0; t < T; t++) {
        if (t + 1 < T) {
            ra0 = *(const float4*)(Ap0 + (t+1)*32);
            ra1 = *(const float4*)(Ap1 + (t+1)*32);
            rw0 = *(const float4*)(Wp0 + (t+1)*32);
            rw1 = *(const float4*)(Wp1 + (t+1)*32);
        }
        const bh *Ah = TILE(buf,0), *Al = TILE(buf,1);
        const bh *Wh = TILE(buf,2), *Wl = TILE(buf,3);
        #pragma unroll
        for (int kk = 0; kk < 32; kk += 16) {
            wmma::fragment<wmma::matrix_a, 16, 16, 16, bh, wmma::row_major> ah, al;
            wmma::load_matrix_sync(ah, Ah + (wm*16)*40 + kk, 40);
            wmma::load_matrix_sync(al, Al + (wm*16)*40 + kk, 40);
            #pragma unroll
            for (int j = 0; j < 2; j++) {
                wmma::fragment<wmma::matrix_b, 16, 16, 16, bh, wmma::col_major> bhf, blf;
                wmma::load_matrix_sync(bhf, Wh + (wn*32 + j*16)*40 + kk, 40);
                wmma::load_matrix_sync(blf, Wl + (wn*32 + j*16)*40 + kk, 40);
                wmma::mma_sync(cf[j], ah, bhf, cf[j]);   // hi*hi
                wmma::mma_sync(cf[j], al, bhf, cf[j]);   // lo*hi
                wmma::mma_sync(cf[j], ah, blf, cf[j]);   // hi*lo
            }
        }
        if (t + 1 < T) {
            // buf^1 was last read in iteration t-1 (all warps past that sync)
            int nb = buf ^ 1;
            bh *Ah2 = TILE(nb,0), *Al2 = TILE(nb,1), *Wh2 = TILE(nb,2), *Wl2 = TILE(nb,3);
            cvt8(Ah2 + r0*40 + c,      Al2 + r0*40 + c,      ra0);
            cvt8(Ah2 + (r0+32)*40 + c, Al2 + (r0+32)*40 + c, ra1);
            cvt8(Wh2 + r0*40 + c,      Wl2 + r0*40 + c,      rw0);
            cvt8(Wh2 + (r0+32)*40 + c, Wl2 + (r0+32)*40 + c, rw1);
            __syncthreads();
            buf = nb;
        }
    }
    #undef TILE

    __syncthreads();   // all tile reads done before aliasing Cs over tiles
    wmma::store_matrix_sync(&Cs[wm*16][wn*32],      cf[0], 68, wmma::mem_row_major);
    wmma::store_matrix_sync(&Cs[wm*16][wn*32 + 16], cf[1], 68, wmma::mem_row_major);
    __syncthreads();

    const int row = tid >> 2;
    const int cb  = (tid & 3) * 16;
    const int m = m0 + row;
    #pragma unroll
    for (int i = 0; i < 4; i++) {
        int cc = cb + i * 4;
        float4 v = *(const float4*)(&Cs[row][cc]);
        int n = n0 + cc;
        v.x += bias[n]; v.y += bias[n+1]; v.z += bias[n+2]; v.w += bias[n+3];
        if (RELU) {
            v.x = fmaxf(v.x, 0.f); v.y = fmaxf(v.y, 0.f);
            v.z = fmaxf(v.z, 0.f); v.w = fmaxf(v.w, 0.f);
        }
        if (SPLIT) {
            if (n < 256) *(float4*)(C0 + m * 256 + n) = v;
            else         *(float4*)(C1 + m * 256 + n - 256) = v;
        } else {
            *(float4*)(C0 + m * N + n) = v;
        }
    }
}

// ---------------------------------------------------------------------------
// Weight/bias combine (fp32, exact):
//  Wq' = Wq@Ws, W1' = W1@Wao, Wk' = Wk@Wt, Wv' = Wv@Wt  (4 x 256^3 NN GEMMs)
//  bq' = Wq@bs+bq, b1' = W1@bao+b1, bk' = Wk@bt+bk, bv' = Wv@bt+bv
// Grid = 65 blocks (4*16 tiles + 1 bias block).
// ---------------------------------------------------------------------------
__global__ void __launch_bounds__(256) combine_kernel(
    const float* __restrict__ Win, const float* __restrict__ Ws,
    const float* __restrict__ bin, const float* __restrict__ bsv,
    const float* __restrict__ W1,  const float* __restrict__ Wao,
    const float* __restrict__ b1,  const float* __restrict__ bao,
    const float* __restrict__ Wt,  const float* __restrict__ bt,
    float* __restrict__ Wqp,  float* __restrict__ bqp,
    float* __restrict__ W1p,  float* __restrict__ b1p,
    float* __restrict__ Wkvp, float* __restrict__ bkvp)
{
    const int bid = blockIdx.x;
    if (bid == 64) {
        int i = threadIdx.x;
        if (i < HH) {
            const float* Wq = Win;
            const float* Wk = Win + HH*HH;
            const float* Wv = Win + 2*HH*HH;
            float aq = bin[i], a1 = b1[i], ak = bin[HH + i], av = bin[2*HH + i];
            #pragma unroll 4
            for (int k = 0; k < HH; k++) {
                aq += Wq[i*HH + k] * bsv[k];
                a1 += W1[i*HH + k] * bao[k];
                ak += Wk[i*HH + k] * bt[k];
                av += Wv[i*HH + k] * bt[k];
            }
            bqp[i] = aq; b1p[i] = a1; bkvp[i] = ak; bkvp[HH + i] = av;
        }
        return;
    }
    const int part = bid >> 4;   // 0:Wq' 1:W1' 2:Wk' 3:Wv'
    const float* Am = (part == 0) ? Win : (part == 1) ? W1
                    : (part == 2) ? (Win + HH*HH) : (Win + 2*HH*HH);
    const float* Bm = (part == 0) ? Ws : (part == 1) ? Wao : Wt;
    float*       Cm = (part == 0) ? Wqp : (part == 1) ? W1p
                    : (part == 2) ? Wkvp : (Wkvp + HH*HH);
    const int lb = bid & 15;
    const int m0 = (lb >> 2) * 64;
    const int n0 = (lb & 3) * 64;

    __shared__ __align__(16) float As[16][68];
    __shared__ __align__(16) float Bsm[16][68];
    const int tid = threadIdx.x;
    const int tx = tid & 15;
    const int ty = tid >> 4;
    const int lr = tid >> 2;
    const int lc = (tid & 3) * 4;
    const int br = tid >> 4;
    const int bc = (tid & 15) * 4;

    float acc[4][4] = {};
    for (int k0 = 0; k0 < HH; k0 += 16) {
        float4 af = *(const float4*)(Am + (m0 + lr) * HH + k0 + lc);
        float4 bf = *(const float4*)(Bm + (k0 + br) * HH + n0 + bc);
        As[lc+0][lr] = af.x; As[lc+1][lr] = af.y;
        As[lc+2][lr] = af.z; As[lc+3][lr] = af.w;
        *(float4*)(&Bsm[br][bc]) = bf;
        __syncthreads();
        #pragma unroll
        for (int kk = 0; kk < 16; kk++) {
            float4 a4 = *(const float4*)(&As[kk][ty * 4]);
            float4 b4 = *(const float4*)(&Bsm[kk][tx * 4]);
            float ar[4] = {a4.x, a4.y, a4.z, a4.w};
            float brr[4] = {b4.x, b4.y, b4.z, b4.w};
            #pragma unroll
            for (int i = 0; i < 4; i++)
                #pragma unroll
                for (int j = 0; j < 4; j++)
                    acc[i][j] += ar[i] * brr[j];
        }
        __syncthreads();
    }
    #pragma unroll
    for (int i = 0; i < 4; i++)
        #pragma unroll
        for (int j = 0; j < 4; j++)
            Cm[(m0 + ty * 4 + i) * HH + n0 + tx * 4 + j] = acc[i][j];
}

// ---------------------------------------------------------------------------
// Attention: per (b,h) block loads K/V head tiles into smem; warp-per-query.
// ---------------------------------------------------------------------------
__global__ void __launch_bounds__(128) attn_kernel(
    const float* __restrict__ q, const float* __restrict__ k,
    const float* __restrict__ v, float* __restrict__ ctx)
{
    __shared__ float ks[SS][33];
    __shared__ float vs[SS][33];
    __shared__ float attn[4][SS];

    const int b = blockIdx.x >> 3;
    const int h = blockIdx.x & 7;
    const int n0 = blockIdx.y * 128;
    const int tid = threadIdx.x;
    const int w = tid >> 5;
    const int lane = tid & 31;

    for (int idx = tid; idx < SS * 32; idx += 128) {
        int s = idx >> 5, d = idx & 31;
        int src = (b * SS + s) * HH + h * HDD + d;
        ks[s][d] = k[src];
        vs[s][d] = v[src];
    }
    __syncthreads();

    const float scale = 0.17677669529663687f;  // 1/sqrt(32)

    for (int nl = w; nl < 128; nl += 4) {
        const int row = b * NN + n0 + nl;
        float qd = q[row * HH + h * HDD + lane] * scale;

        float acc0 = 0.f, acc1 = 0.f, acc2 = 0.f;
        #pragma unroll
        for (int d = 0; d < 32; d++) {
            float qv = __shfl_sync(0xffffffffu, qd, d);
            acc0 += qv * ks[lane][d];
            acc1 += qv * ks[lane + 32][d];
            acc2 += qv * ks[lane + 64][d];
        }
        float m = fmaxf(acc0, fmaxf(acc1, acc2));
        #pragma unroll
        for (int o = 16; o; o >>= 1) m = fmaxf(m, __shfl_xor_sync(0xffffffffu, m, o));
        float e0 = __expf(acc0 - m);
        float e1 = __expf(acc1 - m);
        float e2 = __expf(acc2 - m);
        float sum = e0 + e1 + e2;
        #pragma unroll
        for (int o = 16; o; o >>= 1) sum += __shfl_xor_sync(0xffffffffu, sum, o);
        float inv = 1.0f / sum;

        attn[w][lane]      = e0 * inv;
        attn[w][lane + 32] = e1 * inv;
        attn[w][lane + 64] = e2 * inv;
        __syncwarp();

        float cd = 0.f;
        #pragma unroll 8
        for (int s = 0; s < SS; s++) cd += attn[w][s] * vs[s][lane];
        ctx[row * HH + h * HDD + lane] = cd;
        __syncwarp();
    }
}

// ---------------------------------------------------------------------------
// Fused y = h2 @ Wo2.T + bo2 and broadcast to out[b,s,n,:4].
// One warp per (b,n) row: 4 dot products (K=128), butterfly reduce, then
// 96 float4 stores (one per s).
// ---------------------------------------------------------------------------
__global__ void __launch_bounds__(256) ybcast_kernel(
    const float* __restrict__ h2, const float* __restrict__ Wo2,
    const float* __restrict__ bo2, float4* __restrict__ out4)
{
    const int gw = (blockIdx.x * 256 + threadIdx.x) >> 5;  // 0..4095 = (b,n)
    const int lane = threadIdx.x & 31;
    const int b = gw >> 9;
    const int n = gw & (NN - 1);

    const float* hr = h2 + gw * (HH/2);
    float h0 = hr[lane], h1 = hr[lane + 32], h2v = hr[lane + 64], h3 = hr[lane + 96];

    float4 y;
    float* yp = (float*)&y;
    #pragma unroll
    for (int o = 0; o < OUTD; o++) {
        const float* w = Wo2 + o * (HH/2);
        float p = h0 * w[lane] + h1 * w[lane + 32] + h2v * w[lane + 64] + h3 * w[lane + 96];
        #pragma unroll
        for (int off = 16; off; off >>= 1) p += __shfl_xor_sync(0xffffffffu, p, off);
        yp[o] = p + bo2[o];
    }

    #pragma unroll
    for (int i = 0; i < 3; i++) {
        int s = lane + i * 32;
        out4[(b * SS + s) * NN + n] = y;
    }
}

extern "C" void kernel_launch(void* const* d_in, const int* in_sizes, int n_in,
                              void* d_out, int out_size)
{
    const float* spatial  = (const float*)d_in[0];
    const float* temporal = (const float*)d_in[1];
    const float* Ws  = (const float*)d_in[2];
    const float* bs  = (const float*)d_in[3];
    const float* Wt  = (const float*)d_in[4];
    const float* bt  = (const float*)d_in[5];
    const float* Win = (const float*)d_in[6];
    const float* bin = (const float*)d_in[7];
    const float* Wao = (const float*)d_in[8];
    const float* bao = (const float*)d_in[9];
    const float* W1  = (const float*)d_in[10];
    const float* b1  = (const float*)d_in[11];
    const float* Wo1 = (const float*)d_in[12];
    const float* bo1 = (const float*)d_in[13];
    const float* Wo2 = (const float*)d_in[14];
    const float* bo2 = (const float*)d_in[15];
    float* out = (float*)d_out;

    float *Wqp, *bqp, *W1p, *b1p, *Wkvp, *bkvp, *qb, *kb, *vb, *ctx, *fu, *h2;
    cudaGetSymbolAddress((void**)&Wqp,  g_Wqp);
    cudaGetSymbolAddress((void**)&bqp,  g_bqp);
    cudaGetSymbolAddress((void**)&W1p,  g_W1p);
    cudaGetSymbolAddress((void**)&b1p,  g_b1p);
    cudaGetSymbolAddress((void**)&Wkvp, g_Wkvp);
    cudaGetSymbolAddress((void**)&bkvp, g_bkvp);
    cudaGetSymbolAddress((void**)&qb,   g_q);
    cudaGetSymbolAddress((void**)&kb,   g_k);
    cudaGetSymbolAddress((void**)&vb,   g_v);
    cudaGetSymbolAddress((void**)&ctx,  g_ctx);
    cudaGetSymbolAddress((void**)&fu,   g_fu);
    cudaGetSymbolAddress((void**)&h2,   g_h2);

    // Fold all linear-linear chains (q, k, v, fused): 4 weight products + biases
    combine_kernel<<<65, 256>>>(Win, Ws, bin, bs, W1, Wao, b1, bao, Wt, bt,
                                Wqp, bqp, W1p, b1p, Wkvp, bkvp);

    // k|v = temporal @ Wkv'.T + bkv'  (768 x 512 -> split k,v)
    gemm_bf16<0,1><<<dim3(8, MK/64), 256>>>(temporal, Wkvp, bkvp, kb, vb, MK, 2*HH, HH);

    // q = spatial @ Wq'.T + bq'  (4096 x 256)
    gemm_bf16<0,0><<<dim3(4, MQ/64), 256>>>(spatial, Wqp, bqp, qb, nullptr, MQ, HH, HH);

    // attention -> ctx
    attn_kernel<<<dim3(BB*NHH, NN/128), 128>>>(qb, kb, vb, ctx);

    // fused = relu(ctx @ W1'.T + b1')  (4096 x 256)
    gemm_bf16<1,0><<<dim3(4, MQ/64), 256>>>(ctx, W1p, b1p, fu, nullptr, MQ, HH, HH);

    // h2 = relu(fused @ Wo1.T + bo1)  (4096 x 128)
    gemm_bf16<1,0><<<dim3(2, MQ/64), 256>>>(fu, Wo1, bo1, h2, nullptr, MQ, HH/2, HH);

    // y = h2 @ Wo2.T + bo2 fused with broadcast
    ybcast_kernel<<<512, 256>>>(h2, Wo2, bo2, (float4*)out);
}

// round 7
// speedup vs baseline: 1.0022x; 1.0022x over previous
#include <cuda_runtime.h>
#include <cuda_bf16.h>
#include <mma.h>

using namespace nvcuda;
typedef __nv_bfloat16 bh;

// Problem constants
#define BB 8
#define NN 512
#define SS 96
#define HH 256
#define NHH 8
#define HDD 32
#define OUTD 4
#define MQ (BB*NN)   // 4096
#define MK (BB*SS)   // 768

// Scratch (device globals — no allocation allowed)
__device__ float g_Wqp[HH*HH];       // Wq @ Ws
__device__ float g_bqp[HH];
__device__ float g_W1p[HH*HH];       // W1 @ Wao
__device__ float g_b1p[HH];
__device__ float g_Wkvp[2*HH*HH];    // [Wk@Wt ; Wv@Wt]
__device__ float g_bkvp[2*HH];
__device__ float g_q [MQ*HH];
__device__ float g_k [MK*HH];
__device__ float g_v [MK*HH];
__device__ float g_ctx[MQ*HH];
__device__ float g_fu [MQ*HH];
__device__ float g_h2 [MQ*(HH/2)];

// ---------------------------------------------------------------------------
// fp32 -> (hi, lo) bf16 split, packed 4-wide into two 8B smem stores.
// ---------------------------------------------------------------------------
__device__ __forceinline__ void cvt8(bh* ph, bh* pl, float4 v) {
    float x[4] = {v.x, v.y, v.z, v.w};
    unsigned h[4], l[4];
    #pragma unroll
    for (int i = 0; i < 4; i++) {
        __nv_bfloat16 hb = __float2bfloat16(x[i]);
        float r = x[i] - __bfloat162float(hb);
        __nv_bfloat16 lb = __float2bfloat16(r);
        h[i] = __bfloat16_as_ushort(hb);
        l[i] = __bfloat16_as_ushort(lb);
    }
    uint2 hv = make_uint2(h[0] | (h[1] << 16), h[2] | (h[3] << 16));
    uint2 lv = make_uint2(l[0] | (l[1] << 16), l[2] | (l[3] << 16));
    *(uint2*)ph = hv;
    *(uint2*)pl = lv;
}

// ---------------------------------------------------------------------------
// Tensor-core NT GEMM with fp32->bf16 hi/lo split (3-product compensation).
// C[m,n] = sum_k A[m,k]*W[n,k] + bias[n]  (optional ReLU; optional col split)
// A:(M,K) rm fp32, W:(N,K) rm fp32. M%64==0, N%64==0, K%32==0.
// 256 thr = 8 warps; 64x64 tile; warp = 16x32 via 2 wmma 16x16x16 frags.
// Per 32-wide fp32 k-chunk: products hi*hi + lo*hi + hi*lo on HMMA.
// Double-buffered smem; staging epilogue aliased over tile smem.
// ---------------------------------------------------------------------------
template<int RELU, int SPLIT>
__global__ void __launch_bounds__(256) gemm_bf16(
    const float* __restrict__ A, const float* __restrict__ Wg,
    const float* __restrict__ bias, float* __restrict__ C0,
    float* __restrict__ C1, int M, int N, int K)
{
    __shared__ __align__(16) char smem_raw[40960];  // 2 bufs x 4 mats x 64x40 bf16
    bh* sb = (bh*)smem_raw;
    float (*Cs)[68] = (float(*)[68])smem_raw;       // 64x68 fp32 staging (alias)

    const int n0 = blockIdx.x * 64;
    const int m0 = blockIdx.y * 64;
    const int tid = threadIdx.x;
    const int wid = tid >> 5;
    const int wm = wid >> 1;          // 0..3 : warp m-tile (16 rows)
    const int wn = wid & 1;           // 0..1 : warp n-tile (32 cols)
    const int r0 = tid >> 3;          // 0..31 : load row
    const int c  = (tid & 7) * 4;     // 0..28 : load k offset

    const float* Ap0 = A  + (m0 + r0) * K + c;
    const float* Ap1 = A  + (m0 + r0 + 32) * K + c;
    const float* Wp0 = Wg + (n0 + r0) * K + c;
    const float* Wp1 = Wg + (n0 + r0 + 32) * K + c;

    wmma::fragment<wmma::accumulator, 16, 16, 16, float> cf[2];
    wmma::fill_fragment(cf[0], 0.0f);
    wmma::fill_fragment(cf[1], 0.0f);

    float4 ra0 = *(const float4*)Ap0;
    float4 ra1 = *(const float4*)Ap1;
    float4 rw0 = *(const float4*)Wp0;
    float4 rw1 = *(const float4*)Wp1;

    // tile(buf, mat): mat 0=Ah 1=Al 2=Wh 3=Wl ; each 64 rows x 40 bf16
    #define TILE(buf, mat) (sb + (((buf)*4 + (mat)) * 64 * 40))

    // stash chunk 0
    {
        bh *Ah = TILE(0,0), *Al = TILE(0,1), *Wh = TILE(0,2), *Wl = TILE(0,3);
        cvt8(Ah + r0*40 + c,      Al + r0*40 + c,      ra0);
        cvt8(Ah + (r0+32)*40 + c, Al + (r0+32)*40 + c, ra1);
        cvt8(Wh + r0*40 + c,      Wl + r0*40 + c,      rw0);
        cvt8(Wh + (r0+32)*40 + c, Wl + (r0+32)*40 + c, rw1);
    }
    __syncthreads();

    const int T = K >> 5;
    int buf = 0;
    for (int t = 0; t < T; t++) {
        if (t + 1 < T) {
            ra0 = *(const float4*)(Ap0 + (t+1)*32);
            ra1 = *(const float4*)(Ap1 + (t+1)*32);
            rw0 = *(const float4*)(Wp0 + (t+1)*32);
            rw1 = *(const float4*)(Wp1 + (t+1)*32);
        }
        const bh *Ah = TILE(buf,0), *Al = TILE(buf,1);
        const bh *Wh = TILE(buf,2), *Wl = TILE(buf,3);
        #pragma unroll
        for (int kk = 0; kk < 32; kk += 16) {
            wmma::fragment<wmma::matrix_a, 16, 16, 16, bh, wmma::row_major> ah, al;
            wmma::load_matrix_sync(ah, Ah + (wm*16)*40 + kk, 40);
            wmma::load_matrix_sync(al, Al + (wm*16)*40 + kk, 40);
            #pragma unroll
            for (int j = 0; j < 2; j++) {
                wmma::fragment<wmma::matrix_b, 16, 16, 16, bh, wmma::col_major> bhf, blf;
                wmma::load_matrix_sync(bhf, Wh + (wn*32 + j*16)*40 + kk, 40);
                wmma::load_matrix_sync(blf, Wl + (wn*32 + j*16)*40 + kk, 40);
                wmma::mma_sync(cf[j], ah, bhf, cf[j]);   // hi*hi
                wmma::mma_sync(cf[j], al, bhf, cf[j]);   // lo*hi
                wmma::mma_sync(cf[j], ah, blf, cf[j]);   // hi*lo
            }
        }
        if (t + 1 < T) {
            // buf^1 was last read in iteration t-1 (all warps past that sync)
            int nb = buf ^ 1;
            bh *Ah2 = TILE(nb,0), *Al2 = TILE(nb,1), *Wh2 = TILE(nb,2), *Wl2 = TILE(nb,3);
            cvt8(Ah2 + r0*40 + c,      Al2 + r0*40 + c,      ra0);
            cvt8(Ah2 + (r0+32)*40 + c, Al2 + (r0+32)*40 + c, ra1);
            cvt8(Wh2 + r0*40 + c,      Wl2 + r0*40 + c,      rw0);
            cvt8(Wh2 + (r0+32)*40 + c, Wl2 + (r0+32)*40 + c, rw1);
            __syncthreads();
            buf = nb;
        }
    }
    #undef TILE

    __syncthreads();   // all tile reads done before aliasing Cs over tiles
    wmma::store_matrix_sync(&Cs[wm*16][wn*32],      cf[0], 68, wmma::mem_row_major);
    wmma::store_matrix_sync(&Cs[wm*16][wn*32 + 16], cf[1], 68, wmma::mem_row_major);
    __syncthreads();

    const int row = tid >> 2;
    const int cb  = (tid & 3) * 16;
    const int m = m0 + row;
    #pragma unroll
    for (int i = 0; i < 4; i++) {
        int cc = cb + i * 4;
        float4 v = *(const float4*)(&Cs[row][cc]);
        int n = n0 + cc;
        v.x += bias[n]; v.y += bias[n+1]; v.z += bias[n+2]; v.w += bias[n+3];
        if (RELU) {
            v.x = fmaxf(v.x, 0.f); v.y = fmaxf(v.y, 0.f);
            v.z = fmaxf(v.z, 0.f); v.w = fmaxf(v.w, 0.f);
        }
        if (SPLIT) {
            if (n < 256) *(float4*)(C0 + m * 256 + n) = v;
            else         *(float4*)(C1 + m * 256 + n - 256) = v;
        } else {
            *(float4*)(C0 + m * N + n) = v;
        }
    }
}

// ---------------------------------------------------------------------------
// Weight/bias combine (fp32, exact):
//  Wq' = Wq@Ws, W1' = W1@Wao, Wk' = Wk@Wt, Wv' = Wv@Wt  (4 x 256^3 NN GEMMs)
//  bq' = Wq@bs+bq, b1' = W1@bao+b1, bk' = Wk@bt+bk, bv' = Wv@bt+bv
// Grid = 65 blocks (4*16 tiles + 1 bias block).
// ---------------------------------------------------------------------------
__global__ void __launch_bounds__(256) combine_kernel(
    const float* __restrict__ Win, const float* __restrict__ Ws,
    const float* __restrict__ bin, const float* __restrict__ bsv,
    const float* __restrict__ W1,  const float* __restrict__ Wao,
    const float* __restrict__ b1,  const float* __restrict__ bao,
    const float* __restrict__ Wt,  const float* __restrict__ bt,
    float* __restrict__ Wqp,  float* __restrict__ bqp,
    float* __restrict__ W1p,  float* __restrict__ b1p,
    float* __restrict__ Wkvp, float* __restrict__ bkvp)
{
    const int bid = blockIdx.x;
    if (bid == 64) {
        int i = threadIdx.x;
        if (i < HH) {
            const float* Wq = Win;
            const float* Wk = Win + HH*HH;
            const float* Wv = Win + 2*HH*HH;
            float aq = bin[i], a1 = b1[i], ak = bin[HH + i], av = bin[2*HH + i];
            #pragma unroll 4
            for (int k = 0; k < HH; k++) {
                aq += Wq[i*HH + k] * bsv[k];
                a1 += W1[i*HH + k] * bao[k];
                ak += Wk[i*HH + k] * bt[k];
                av += Wv[i*HH + k] * bt[k];
            }
            bqp[i] = aq; b1p[i] = a1; bkvp[i] = ak; bkvp[HH + i] = av;
        }
        return;
    }
    const int part = bid >> 4;   // 0:Wq' 1:W1' 2:Wk' 3:Wv'
    const float* Am = (part == 0) ? Win : (part == 1) ? W1
                    : (part == 2) ? (Win + HH*HH) : (Win + 2*HH*HH);
    const float* Bm = (part == 0) ? Ws : (part == 1) ? Wao : Wt;
    float*       Cm = (part == 0) ? Wqp : (part == 1) ? W1p
                    : (part == 2) ? Wkvp : (Wkvp + HH*HH);
    const int lb = bid & 15;
    const int m0 = (lb >> 2) * 64;
    const int n0 = (lb & 3) * 64;

    __shared__ __align__(16) float As[16][68];
    __shared__ __align__(16) float Bsm[16][68];
    const int tid = threadIdx.x;
    const int tx = tid & 15;
    const int ty = tid >> 4;
    const int lr = tid >> 2;
    const int lc = (tid & 3) * 4;
    const int br = tid >> 4;
    const int bc = (tid & 15) * 4;

    float acc[4][4] = {};
    for (int k0 = 0; k0 < HH; k0 += 16) {
        float4 af = *(const float4*)(Am + (m0 + lr) * HH + k0 + lc);
        float4 bf = *(const float4*)(Bm + (k0 + br) * HH + n0 + bc);
        As[lc+0][lr] = af.x; As[lc+1][lr] = af.y;
        As[lc+2][lr] = af.z; As[lc+3][lr] = af.w;
        *(float4*)(&Bsm[br][bc]) = bf;
        __syncthreads();
        #pragma unroll
        for (int kk = 0; kk < 16; kk++) {
            float4 a4 = *(const float4*)(&As[kk][ty * 4]);
            float4 b4 = *(const float4*)(&Bsm[kk][tx * 4]);
            float ar[4] = {a4.x, a4.y, a4.z, a4.w};
            float brr[4] = {b4.x, b4.y, b4.z, b4.w};
            #pragma unroll
            for (int i = 0; i < 4; i++)
                #pragma unroll
                for (int j = 0; j < 4; j++)
                    acc[i][j] += ar[i] * brr[j];
        }
        __syncthreads();
    }
    #pragma unroll
    for (int i = 0; i < 4; i++)
        #pragma unroll
        for (int j = 0; j < 4; j++)
            Cm[(m0 + ty * 4 + i) * HH + n0 + tx * 4 + j] = acc[i][j];
}

// ---------------------------------------------------------------------------
// Attention: per (b,h) block loads K/V head tiles into smem; warp-per-query.
// ---------------------------------------------------------------------------
__global__ void __launch_bounds__(128) attn_kernel(
    const float* __restrict__ q, const float* __restrict__ k,
    const float* __restrict__ v, float* __restrict__ ctx)
{
    __shared__ float ks[SS][33];
    __shared__ float vs[SS][33];
    __shared__ float attn[4][SS];

    const int b = blockIdx.x >> 3;
    const int h = blockIdx.x & 7;
    const int n0 = blockIdx.y * 128;
    const int tid = threadIdx.x;
    const int w = tid >> 5;
    const int lane = tid & 31;

    for (int idx = tid; idx < SS * 32; idx += 128) {
        int s = idx >> 5, d = idx & 31;
        int src = (b * SS + s) * HH + h * HDD + d;
        ks[s][d] = k[src];
        vs[s][d] = v[src];
    }
    __syncthreads();

    const float scale = 0.17677669529663687f;  // 1/sqrt(32)

    for (int nl = w; nl < 128; nl += 4) {
        const int row = b * NN + n0 + nl;
        float qd = q[row * HH + h * HDD + lane] * scale;

        float acc0 = 0.f, acc1 = 0.f, acc2 = 0.f;
        #pragma unroll
        for (int d = 0; d < 32; d++) {
            float qv = __shfl_sync(0xffffffffu, qd, d);
            acc0 += qv * ks[lane][d];
            acc1 += qv * ks[lane + 32][d];
            acc2 += qv * ks[lane + 64][d];
        }
        float m = fmaxf(acc0, fmaxf(acc1, acc2));
        #pragma unroll
        for (int o = 16; o; o >>= 1) m = fmaxf(m, __shfl_xor_sync(0xffffffffu, m, o));
        float e0 = __expf(acc0 - m);
        float e1 = __expf(acc1 - m);
        float e2 = __expf(acc2 - m);
        float sum = e0 + e1 + e2;
        #pragma unroll
        for (int o = 16; o; o >>= 1) sum += __shfl_xor_sync(0xffffffffu, sum, o);
        float inv = 1.0f / sum;

        attn[w][lane]      = e0 * inv;
        attn[w][lane + 32] = e1 * inv;
        attn[w][lane + 64] = e2 * inv;
        __syncwarp();

        float cd = 0.f;
        #pragma unroll 8
        for (int s = 0; s < SS; s++) cd += attn[w][s] * vs[s][lane];
        ctx[row * HH + h * HDD + lane] = cd;
        __syncwarp();
    }
}

// ---------------------------------------------------------------------------
// Fused y = h2 @ Wo2.T + bo2 and broadcast to out[b,s,n,:4].
// One warp per (b,n) row: 4 dot products (K=128), butterfly reduce, then
// 96 float4 stores (one per s).
// ---------------------------------------------------------------------------
__global__ void __launch_bounds__(256) ybcast_kernel(
    const float* __restrict__ h2, const float* __restrict__ Wo2,
    const float* __restrict__ bo2, float4* __restrict__ out4)
{
    const int gw = (blockIdx.x * 256 + threadIdx.x) >> 5;  // 0..4095 = (b,n)
    const int lane = threadIdx.x & 31;
    const int b = gw >> 9;
    const int n = gw & (NN - 1);

    const float* hr = h2 + gw * (HH/2);
    float h0 = hr[lane], h1 = hr[lane + 32], h2v = hr[lane + 64], h3 = hr[lane + 96];

    float4 y;
    float* yp = (float*)&y;
    #pragma unroll
    for (int o = 0; o < OUTD; o++) {
        const float* w = Wo2 + o * (HH/2);
        float p = h0 * w[lane] + h1 * w[lane + 32] + h2v * w[lane + 64] + h3 * w[lane + 96];
        #pragma unroll
        for (int off = 16; off; off >>= 1) p += __shfl_xor_sync(0xffffffffu, p, off);
        yp[o] = p + bo2[o];
    }

    #pragma unroll
    for (int i = 0; i < 3; i++) {
        int s = lane + i * 32;
        out4[(b * SS + s) * NN + n] = y;
    }
}

extern "C" void kernel_launch(void* const* d_in, const int* in_sizes, int n_in,
                              void* d_out, int out_size)
{
    const float* spatial  = (const float*)d_in[0];
    const float* temporal = (const float*)d_in[1];
    const float* Ws  = (const float*)d_in[2];
    const float* bs  = (const float*)d_in[3];
    const float* Wt  = (const float*)d_in[4];
    const float* bt  = (const float*)d_in[5];
    const float* Win = (const float*)d_in[6];
    const float* bin = (const float*)d_in[7];
    const float* Wao = (const float*)d_in[8];
    const float* bao = (const float*)d_in[9];
    const float* W1  = (const float*)d_in[10];
    const float* b1  = (const float*)d_in[11];
    const float* Wo1 = (const float*)d_in[12];
    const float* bo1 = (const float*)d_in[13];
    const float* Wo2 = (const float*)d_in[14];
    const float* bo2 = (const float*)d_in[15];
    float* out = (float*)d_out;

    float *Wqp, *bqp, *W1p, *b1p, *Wkvp, *bkvp, *qb, *kb, *vb, *ctx, *fu, *h2;
    cudaGetSymbolAddress((void**)&Wqp,  g_Wqp);
    cudaGetSymbolAddress((void**)&bqp,  g_bqp);
    cudaGetSymbolAddress((void**)&W1p,  g_W1p);
    cudaGetSymbolAddress((void**)&b1p,  g_b1p);
    cudaGetSymbolAddress((void**)&Wkvp, g_Wkvp);
    cudaGetSymbolAddress((void**)&bkvp, g_bkvp);
    cudaGetSymbolAddress((void**)&qb,   g_q);
    cudaGetSymbolAddress((void**)&kb,   g_k);
    cudaGetSymbolAddress((void**)&vb,   g_v);
    cudaGetSymbolAddress((void**)&ctx,  g_ctx);
    cudaGetSymbolAddress((void**)&fu,   g_fu);
    cudaGetSymbolAddress((void**)&h2,   g_h2);

    // Fold all linear-linear chains (q, k, v, fused): 4 weight products + biases
    combine_kernel<<<65, 256>>>(Win, Ws, bin, bs, W1, Wao, b1, bao, Wt, bt,
                                Wqp, bqp, W1p, b1p, Wkvp, bkvp);

    // k|v = temporal @ Wkv'.T + bkv'  (768 x 512 -> split k,v)
    gemm_bf16<0,1><<<dim3(8, MK/64), 256>>>(temporal, Wkvp, bkvp, kb, vb, MK, 2*HH, HH);

    // q = spatial @ Wq'.T + bq'  (4096 x 256)
    gemm_bf16<0,0><<<dim3(4, MQ/64), 256>>>(spatial, Wqp, bqp, qb, nullptr, MQ, HH, HH);

    // attention -> ctx
    attn_kernel<<<dim3(BB*NHH, NN/128), 128>>>(qb, kb, vb, ctx);

    // fused = relu(ctx @ W1'.T + b1')  (4096 x 256)
    gemm_bf16<1,0><<<dim3(4, MQ/64), 256>>>(ctx, W1p, b1p, fu, nullptr, MQ, HH, HH);

    // h2 = relu(fused @ Wo1.T + bo1)  (4096 x 128)
    gemm_bf16<1,0><<<dim3(2, MQ/64), 256>>>(fu, Wo1, bo1, h2, nullptr, MQ, HH/2, HH);

    // y = h2 @ Wo2.T + bo2 fused with broadcast
    ybcast_kernel<<<512, 256>>>(h2, Wo2, bo2, (float4*)out);
}

// round 8
// speedup vs baseline: 1.0064x; 1.0042x over previous
#include <cuda_runtime.h>
#include <cuda_bf16.h>

// Problem constants
#define BB 8
#define NN 512
#define SS 96
#define HH 256
#define NHH 8
#define HDD 32
#define OUTD 4
#define MQ (BB*NN)   // 4096
#define MK (BB*SS)   // 768

// Scratch (device globals — no allocation allowed)
__device__ float g_Wqp[HH*HH];       // Wq @ Ws
__device__ float g_bqp[HH];
__device__ float g_W1p[HH*HH];       // W1 @ Wao
__device__ float g_b1p[HH];
__device__ float g_Wkvp[2*HH*HH];    // [Wk@Wt ; Wv@Wt]
__device__ float g_bkvp[2*HH];
__device__ float g_q [MQ*HH];
__device__ float g_k [MK*HH];
__device__ float g_v [MK*HH];
__device__ float g_ctx[MQ*HH];
__device__ float g_fu [MQ*HH];
__device__ float g_h2 [MQ*(HH/2)];

// ---------------------------------------------------------------------------
// NT GEMM (fp32, proven 23.6 TF/s): C[m,n] = sum_k A[m,k]*W[n,k] + bias[n]
// Optional ReLU; optional column split (cols [0,256)->C0, [256,512)->C1).
// 256 thr, 64x64 tile, BK=16, 4x4 micro, double-buffered smem, float4 paths.
// ---------------------------------------------------------------------------
template<int RELU, int SPLIT>
__global__ void __launch_bounds__(256) gemm_nt(
    const float* __restrict__ A, const float* __restrict__ W,
    const float* __restrict__ bias, float* __restrict__ C0,
    float* __restrict__ C1, int M, int N, int K)
{
    __shared__ __align__(16) float As[2][16][68];
    __shared__ __align__(16) float Bs[2][16][68];
    const int n0 = blockIdx.x * 64;
    const int m0 = blockIdx.y * 64;
    const int tid = threadIdx.x;
    const int tx = tid & 15;
    const int ty = tid >> 4;
    const int lr = tid >> 2;
    const int lc = (tid & 3) * 4;

    const float* Ap = A + (m0 + lr) * K + lc;
    const float* Wp = W + (n0 + lr) * K + lc;

    float4 af = *(const float4*)Ap;
    float4 bf = *(const float4*)Wp;
    float acc[4][4] = {};

    As[0][lc+0][lr] = af.x; As[0][lc+1][lr] = af.y;
    As[0][lc+2][lr] = af.z; As[0][lc+3][lr] = af.w;
    Bs[0][lc+0][lr] = bf.x; Bs[0][lc+1][lr] = bf.y;
    Bs[0][lc+2][lr] = bf.z; Bs[0][lc+3][lr] = bf.w;
    __syncthreads();

    const int ktiles = K >> 4;
    int buf = 0;
    for (int t = 0; t < ktiles; t++) {
        if (t + 1 < ktiles) {
            af = *(const float4*)(Ap + (t + 1) * 16);
            bf = *(const float4*)(Wp + (t + 1) * 16);
        }
        #pragma unroll
        for (int kk = 0; kk < 16; kk++) {
            float4 a4 = *(const float4*)(&As[buf][kk][ty * 4]);
            float4 b4 = *(const float4*)(&Bs[buf][kk][tx * 4]);
            float ar[4] = {a4.x, a4.y, a4.z, a4.w};
            float br[4] = {b4.x, b4.y, b4.z, b4.w};
            #pragma unroll
            for (int i = 0; i < 4; i++)
                #pragma unroll
                for (int j = 0; j < 4; j++)
                    acc[i][j] += ar[i] * br[j];
        }
        if (t + 1 < ktiles) {
            int nb = buf ^ 1;
            As[nb][lc+0][lr] = af.x; As[nb][lc+1][lr] = af.y;
            As[nb][lc+2][lr] = af.z; As[nb][lc+3][lr] = af.w;
            Bs[nb][lc+0][lr] = bf.x; Bs[nb][lc+1][lr] = bf.y;
            Bs[nb][lc+2][lr] = bf.z; Bs[nb][lc+3][lr] = bf.w;
            __syncthreads();
            buf = nb;
        }
    }

    #pragma unroll
    for (int i = 0; i < 4; i++) {
        int m = m0 + ty * 4 + i;
        #pragma unroll
        for (int j = 0; j < 4; j++) {
            int n = n0 + tx * 4 + j;
            float v = acc[i][j] + bias[n];
            if (RELU) v = fmaxf(v, 0.0f);
            if (SPLIT) {
                if (n < 256) C0[m * 256 + n] = v;
                else         C1[m * 256 + n - 256] = v;
            } else {
                C0[m * N + n] = v;
            }
        }
    }
}

// ---------------------------------------------------------------------------
// Weight/bias combine (fp32, exact):
//  Wq' = Wq@Ws, W1' = W1@Wao, Wk' = Wk@Wt, Wv' = Wv@Wt  (4 x 256^3 NN GEMMs)
//  bq' = Wq@bs+bq, b1' = W1@bao+b1, bk' = Wk@bt+bk, bv' = Wv@bt+bv
// Grid = 65 blocks (4*16 tiles + 1 bias block).
// ---------------------------------------------------------------------------
__global__ void __launch_bounds__(256) combine_kernel(
    const float* __restrict__ Win, const float* __restrict__ Ws,
    const float* __restrict__ bin, const float* __restrict__ bsv,
    const float* __restrict__ W1,  const float* __restrict__ Wao,
    const float* __restrict__ b1,  const float* __restrict__ bao,
    const float* __restrict__ Wt,  const float* __restrict__ bt,
    float* __restrict__ Wqp,  float* __restrict__ bqp,
    float* __restrict__ W1p,  float* __restrict__ b1p,
    float* __restrict__ Wkvp, float* __restrict__ bkvp)
{
    const int bid = blockIdx.x;
    if (bid == 64) {
        int i = threadIdx.x;
        if (i < HH) {
            const float* Wq = Win;
            const float* Wk = Win + HH*HH;
            const float* Wv = Win + 2*HH*HH;
            float aq = bin[i], a1 = b1[i], ak = bin[HH + i], av = bin[2*HH + i];
            #pragma unroll 4
            for (int k = 0; k < HH; k++) {
                aq += Wq[i*HH + k] * bsv[k];
                a1 += W1[i*HH + k] * bao[k];
                ak += Wk[i*HH + k] * bt[k];
                av += Wv[i*HH + k] * bt[k];
            }
            bqp[i] = aq; b1p[i] = a1; bkvp[i] = ak; bkvp[HH + i] = av;
        }
        return;
    }
    const int part = bid >> 4;   // 0:Wq' 1:W1' 2:Wk' 3:Wv'
    const float* Am = (part == 0) ? Win : (part == 1) ? W1
                    : (part == 2) ? (Win + HH*HH) : (Win + 2*HH*HH);
    const float* Bm = (part == 0) ? Ws : (part == 1) ? Wao : Wt;
    float*       Cm = (part == 0) ? Wqp : (part == 1) ? W1p
                    : (part == 2) ? Wkvp : (Wkvp + HH*HH);
    const int lb = bid & 15;
    const int m0 = (lb >> 2) * 64;
    const int n0 = (lb & 3) * 64;

    __shared__ __align__(16) float As[16][68];
    __shared__ __align__(16) float Bsm[16][68];
    const int tid = threadIdx.x;
    const int tx = tid & 15;
    const int ty = tid >> 4;
    const int lr = tid >> 2;
    const int lc = (tid & 3) * 4;
    const int br = tid >> 4;
    const int bc = (tid & 15) * 4;

    float acc[4][4] = {};
    for (int k0 = 0; k0 < HH; k0 += 16) {
        float4 af = *(const float4*)(Am + (m0 + lr) * HH + k0 + lc);
        float4 bf = *(const float4*)(Bm + (k0 + br) * HH + n0 + bc);
        As[lc+0][lr] = af.x; As[lc+1][lr] = af.y;
        As[lc+2][lr] = af.z; As[lc+3][lr] = af.w;
        *(float4*)(&Bsm[br][bc]) = bf;
        __syncthreads();
        #pragma unroll
        for (int kk = 0; kk < 16; kk++) {
            float4 a4 = *(const float4*)(&As[kk][ty * 4]);
            float4 b4 = *(const float4*)(&Bsm[kk][tx * 4]);
            float ar[4] = {a4.x, a4.y, a4.z, a4.w};
            float brr[4] = {b4.x, b4.y, b4.z, b4.w};
            #pragma unroll
            for (int i = 0; i < 4; i++)
                #pragma unroll
                for (int j = 0; j < 4; j++)
                    acc[i][j] += ar[i] * brr[j];
        }
        __syncthreads();
    }
    #pragma unroll
    for (int i = 0; i < 4; i++)
        #pragma unroll
        for (int j = 0; j < 4; j++)
            Cm[(m0 + ty * 4 + i) * HH + n0 + tx * 4 + j] = acc[i][j];
}

// ---------------------------------------------------------------------------
// Attention v2: grid (B*NH, N/32), 256 threads (8 warps), 4 queries/warp.
// q staged in smem (pre-scaled) -> LDS broadcast replaces per-d shuffles.
// lane = s-index (3 accumulators cover S=96).
// ---------------------------------------------------------------------------
__global__ void __launch_bounds__(256) attn_kernel(
    const float* __restrict__ q, const float* __restrict__ k,
    const float* __restrict__ v, float* __restrict__ ctx)
{
    __shared__ float ks[SS][33];
    __shared__ float vs[SS][33];
    __shared__ float qs[32][33];
    __shared__ float attn[8][SS];

    const int b = blockIdx.x >> 3;
    const int h = blockIdx.x & 7;
    const int n0 = blockIdx.y * 32;
    const int tid = threadIdx.x;
    const int w = tid >> 5;
    const int lane = tid & 31;
    const float scale = 0.17677669529663687f;  // 1/sqrt(32)

    for (int idx = tid; idx < SS * 32; idx += 256) {
        int s = idx >> 5, d = idx & 31;
        int src = (b * SS + s) * HH + h * HDD + d;
        ks[s][d] = k[src];
        vs[s][d] = v[src];
    }
    {
        // 32 query rows x 32 dims = 1024 elements, 4 per thread
        #pragma unroll
        for (int i = 0; i < 4; i++) {
            int idx = tid + i * 256;
            int r = idx >> 5, d = idx & 31;
            qs[r][d] = q[(b * NN + n0 + r) * HH + h * HDD + d] * scale;
        }
    }
    __syncthreads();

    #pragma unroll
    for (int qi = 0; qi < 4; qi++) {
        const int nl = w * 4 + qi;

        float acc0 = 0.f, acc1 = 0.f, acc2 = 0.f;
        #pragma unroll
        for (int d = 0; d < 32; d++) {
            float qv = qs[nl][d];                 // LDS broadcast
            acc0 += qv * ks[lane][d];
            acc1 += qv * ks[lane + 32][d];
            acc2 += qv * ks[lane + 64][d];
        }
        float m = fmaxf(acc0, fmaxf(acc1, acc2));
        #pragma unroll
        for (int o = 16; o; o >>= 1) m = fmaxf(m, __shfl_xor_sync(0xffffffffu, m, o));
        float e0 = __expf(acc0 - m);
        float e1 = __expf(acc1 - m);
        float e2 = __expf(acc2 - m);
        float sum = e0 + e1 + e2;
        #pragma unroll
        for (int o = 16; o; o >>= 1) sum += __shfl_xor_sync(0xffffffffu, sum, o);
        float inv = 1.0f / sum;

        attn[w][lane]      = e0 * inv;
        attn[w][lane + 32] = e1 * inv;
        attn[w][lane + 64] = e2 * inv;
        __syncwarp();

        float cd = 0.f;
        #pragma unroll 8
        for (int s = 0; s < SS; s++) cd += attn[w][s] * vs[s][lane];
        ctx[(b * NN + n0 + nl) * HH + h * HDD + lane] = cd;
        __syncwarp();
    }
}

// ---------------------------------------------------------------------------
// Fused y = h2 @ Wo2.T + bo2 and broadcast to out[b,s,n,:4].
// One warp per (b,n): 4 dots (K=128), butterfly reduce, 96 float4 stores.
// ---------------------------------------------------------------------------
__global__ void __launch_bounds__(256) ybcast_kernel(
    const float* __restrict__ h2, const float* __restrict__ Wo2,
    const float* __restrict__ bo2, float4* __restrict__ out4)
{
    const int gw = (blockIdx.x * 256 + threadIdx.x) >> 5;  // 0..4095 = (b,n)
    const int lane = threadIdx.x & 31;
    const int b = gw >> 9;
    const int n = gw & (NN - 1);

    const float* hr = h2 + gw * (HH/2);
    float h0 = hr[lane], h1 = hr[lane + 32], h2v = hr[lane + 64], h3 = hr[lane + 96];

    float4 y;
    float* yp = (float*)&y;
    #pragma unroll
    for (int o = 0; o < OUTD; o++) {
        const float* w = Wo2 + o * (HH/2);
        float p = h0 * w[lane] + h1 * w[lane + 32] + h2v * w[lane + 64] + h3 * w[lane + 96];
        #pragma unroll
        for (int off = 16; off; off >>= 1) p += __shfl_xor_sync(0xffffffffu, p, off);
        yp[o] = p + bo2[o];
    }

    #pragma unroll
    for (int i = 0; i < 3; i++) {
        int s = lane + i * 32;
        out4[(b * SS + s) * NN + n] = y;
    }
}

extern "C" void kernel_launch(void* const* d_in, const int* in_sizes, int n_in,
                              void* d_out, int out_size)
{
    const float* spatial  = (const float*)d_in[0];
    const float* temporal = (const float*)d_in[1];
    const float* Ws  = (const float*)d_in[2];
    const float* bs  = (const float*)d_in[3];
    const float* Wt  = (const float*)d_in[4];
    const float* bt  = (const float*)d_in[5];
    const float* Win = (const float*)d_in[6];
    const float* bin = (const float*)d_in[7];
    const float* Wao = (const float*)d_in[8];
    const float* bao = (const float*)d_in[9];
    const float* W1  = (const float*)d_in[10];
    const float* b1  = (const float*)d_in[11];
    const float* Wo1 = (const float*)d_in[12];
    const float* bo1 = (const float*)d_in[13];
    const float* Wo2 = (const float*)d_in[14];
    const float* bo2 = (const float*)d_in[15];
    float* out = (float*)d_out;

    float *Wqp, *bqp, *W1p, *b1p, *Wkvp, *bkvp, *qb, *kb, *vb, *ctx, *fu, *h2;
    cudaGetSymbolAddress((void**)&Wqp,  g_Wqp);
    cudaGetSymbolAddress((void**)&bqp,  g_bqp);
    cudaGetSymbolAddress((void**)&W1p,  g_W1p);
    cudaGetSymbolAddress((void**)&b1p,  g_b1p);
    cudaGetSymbolAddress((void**)&Wkvp, g_Wkvp);
    cudaGetSymbolAddress((void**)&bkvp, g_bkvp);
    cudaGetSymbolAddress((void**)&qb,   g_q);
    cudaGetSymbolAddress((void**)&kb,   g_k);
    cudaGetSymbolAddress((void**)&vb,   g_v);
    cudaGetSymbolAddress((void**)&ctx,  g_ctx);
    cudaGetSymbolAddress((void**)&fu,   g_fu);
    cudaGetSymbolAddress((void**)&h2,   g_h2);

    // Fold all linear-linear chains (q, k, v, fused): 4 weight products + biases
    combine_kernel<<<65, 256>>>(Win, Ws, bin, bs, W1, Wao, b1, bao, Wt, bt,
                                Wqp, bqp, W1p, b1p, Wkvp, bkvp);

    // k|v = temporal @ Wkv'.T + bkv'  (768 x 512 -> split k,v)
    gemm_nt<0,1><<<dim3(8, MK/64), 256>>>(temporal, Wkvp, bkvp, kb, vb, MK, 2*HH, HH);

    // q = spatial @ Wq'.T + bq'  (4096 x 256)
    gemm_nt<0,0><<<dim3(4, MQ/64), 256>>>(spatial, Wqp, bqp, qb, nullptr, MQ, HH, HH);

    // attention -> ctx
    attn_kernel<<<dim3(BB*NHH, NN/32), 256>>>(qb, kb, vb, ctx);

    // fused = relu(ctx @ W1'.T + b1')  (4096 x 256)
    gemm_nt<1,0><<<dim3(4, MQ/64), 256>>>(ctx, W1p, b1p, fu, nullptr, MQ, HH, HH);

    // h2 = relu(fused @ Wo1.T + bo1)  (4096 x 128)
    gemm_nt<1,0><<<dim3(2, MQ/64), 256>>>(fu, Wo1, bo1, h2, nullptr, MQ, HH/2, HH);

    // y = h2 @ Wo2.T + bo2 fused with broadcast
    ybcast_kernel<<<512, 256>>>(h2, Wo2, bo2, (float4*)out);
}